// round 1
// baseline (speedup 1.0000x reference)
#include <cuda_runtime.h>
#include <math.h>

// Problem constants (fixed by setup_inputs)
#define B_  32
#define K_  16
#define T_  30
#define N_  128
#define n_  20
#define NN  (N_ * n_)        // 2560 nodes per batch
#define KT  (K_ * T_)        // 480 pred points per batch

#define DIST_THRESH 2.0f
#define YAW_THRESH  1.0471975511965976f   // pi/3
#define PI_F        3.14159265358979323846f
#define TWO_PI_F    6.28318530717958647692f

// Scratch: compacted (x, y, yaw, pad) per surviving node, per batch.
__device__ float4 g_compact[B_][NN];
__device__ int    g_cnt[B_];

__device__ __forceinline__ float fast_sqrt(float x) {
    float r;
    asm("sqrt.approx.f32 %0, %1;" : "=f"(r) : "f"(x));
    return r;
}

// -------------------------------------------------------------------------
// Kernel 1: per-batch node preprocessing.
// Computes node yaw (along each centerline of n_ points) and compacts out
// masked nodes (mask == 1 -> cost = inf -> can never win the min).
// Compaction order is arbitrary (atomic), but min() is order-independent,
// so the output stays deterministic.
// -------------------------------------------------------------------------
__global__ void preprocess_nodes(const float* __restrict__ cn,
                                 const int*   __restrict__ mask) {
    const int b = blockIdx.x;
    __shared__ int s_cnt;
    if (threadIdx.x == 0) s_cnt = 0;
    __syncthreads();

    const float* cnb = cn + (size_t)b * NN * 2;
    const int*   mb  = mask + (size_t)b * NN;

    for (int idx = threadIdx.x; idx < NN; idx += blockDim.x) {
        if (mb[idx] != 1) {
            const int i = idx % n_;          // position within centerline
            float x = cnb[idx * 2 + 0];
            float y = cnb[idx * 2 + 1];
            float yaw = 0.0f;
            if (i != 0) {
                float px = cnb[(idx - 1) * 2 + 0];
                float py = cnb[(idx - 1) * 2 + 1];
                yaw = -atan2f(x - px, y - py);
            }
            int pos = atomicAdd(&s_cnt, 1);
            g_compact[b][pos] = make_float4(x, y, yaw, 0.0f);
        }
    }
    __syncthreads();
    if (threadIdx.x == 0) g_cnt[b] = s_cnt;
}

// -------------------------------------------------------------------------
// Kernel 2: main cost/min/sum.
// One block per (b, k). 256 threads = 32 t-groups x 8 node-lanes.
// Node table broadcast-loaded from smem; per-pair:
//   c = relu(|p - node| - 2) + relu(min(|dy|, 2pi-|dy|) - pi/3)
// min over nodes, then sum over T.
// -------------------------------------------------------------------------
__global__ __launch_bounds__(256, 4)
void consistency_main(const float* __restrict__ preds,
                      float* __restrict__ out) {
    const int bk = blockIdx.x;
    const int b  = bk / K_;
    const int k  = bk % K_;

    __shared__ float4 s_nodes[NN];
    __shared__ float  s_px[32], s_py[32], s_pyaw[32];
    __shared__ float  s_tmin[32];

    const int tid = threadIdx.x;
    const int cnt = g_cnt[b];

    // Load compacted node table for this batch.
    for (int i = tid; i < cnt; i += 256)
        s_nodes[i] = g_compact[b][i];

    // Pred points + yaws for this (b, k).
    if (tid < T_) {
        const float* pb = preds + ((size_t)(b * K_ + k) * T_ + tid) * 2;
        float x = pb[0], y = pb[1];
        s_px[tid] = x;
        s_py[tid] = y;
        if (tid == 0) {
            s_pyaw[0] = 0.0f;
        } else {
            float xm = pb[-2], ym = pb[-1];
            s_pyaw[tid] = -atan2f(x - xm, y - ym);
        }
    }
    __syncthreads();

    const int t = tid >> 3;      // 0..31 (0..29 valid)
    const int g = tid & 7;       // node lane within group

    float mymin = INFINITY;
    if (t < T_) {
        const float px   = s_px[t];
        const float py   = s_py[t];
        const float pyaw = s_pyaw[t];

        int j = g;
        // unrolled by 2 for ILP
        for (; j + 8 < cnt; j += 16) {
            float4 nd0 = s_nodes[j];
            float4 nd1 = s_nodes[j + 8];

            float dx0 = nd0.x - px, dy0 = nd0.y - py;
            float dx1 = nd1.x - px, dy1 = nd1.y - py;
            float d0 = fast_sqrt(fmaf(dx0, dx0, dy0 * dy0));
            float d1 = fast_sqrt(fmaf(dx1, dx1, dy1 * dy1));
            float c0 = fmaxf(d0 - DIST_THRESH, 0.0f);
            float c1 = fmaxf(d1 - DIST_THRESH, 0.0f);

            float a0 = fabsf(nd0.z - pyaw);
            float a1 = fabsf(nd1.z - pyaw);
            a0 = fminf(a0, TWO_PI_F - a0);
            a1 = fminf(a1, TWO_PI_F - a1);
            c0 += fmaxf(a0 - YAW_THRESH, 0.0f);
            c1 += fmaxf(a1 - YAW_THRESH, 0.0f);

            mymin = fminf(mymin, fminf(c0, c1));
        }
        if (j < cnt) {
            float4 nd = s_nodes[j];
            float dx = nd.x - px, dy = nd.y - py;
            float d = fast_sqrt(fmaf(dx, dx, dy * dy));
            float c = fmaxf(d - DIST_THRESH, 0.0f);
            float a = fabsf(nd.z - pyaw);
            a = fminf(a, TWO_PI_F - a);
            c += fmaxf(a - YAW_THRESH, 0.0f);
            mymin = fminf(mymin, c);
        }
    }

    // Reduce min over the 8 lanes of each t-group (lanes are consecutive,
    // xor 1/2/4 stays within the group).
    mymin = fminf(mymin, __shfl_xor_sync(0xffffffffu, mymin, 1));
    mymin = fminf(mymin, __shfl_xor_sync(0xffffffffu, mymin, 2));
    mymin = fminf(mymin, __shfl_xor_sync(0xffffffffu, mymin, 4));
    if (g == 0 && t < 32) s_tmin[t] = (t < T_) ? mymin : 0.0f;
    __syncthreads();

    // Warp 0 sums the 30 per-t minima.
    if (tid < 32) {
        float v = s_tmin[tid];
        v += __shfl_xor_sync(0xffffffffu, v, 16);
        v += __shfl_xor_sync(0xffffffffu, v, 8);
        v += __shfl_xor_sync(0xffffffffu, v, 4);
        v += __shfl_xor_sync(0xffffffffu, v, 2);
        v += __shfl_xor_sync(0xffffffffu, v, 1);
        if (tid == 0) out[bk] = v;
    }
}

extern "C" void kernel_launch(void* const* d_in, const int* in_sizes, int n_in,
                              void* d_out, int out_size) {
    const float* preds = (const float*)d_in[0];
    const float* cn    = (const float*)d_in[1];
    const int*   mask  = (const int*)d_in[2];
    float* out = (float*)d_out;

    preprocess_nodes<<<B_, 256>>>(cn, mask);
    consistency_main<<<B_ * K_, 256>>>(preds, out);
}